// round 16
// baseline (speedup 1.0000x reference)
#include <cuda_runtime.h>
#include <cuda_fp16.h>
#include <math.h>
#include <cstdint>

// ---------------------------------------------------------------------------
// B=8, L=2048, D=1024, K=32, J=512; n0=2050, ns=514, n1=2082
// NP=2176 (17*128), NS=640 (5*128). Queries offset 33 -> MQ=2048 rows.
// Schedule (R15 + dedicated build stream s3 + merged wcvt2):
//   s3:   [evFork] build x0h (evX0), xsh (evXB), x1main (evXD)
//   main: evFork, wcvt2(Wq,Wo) (evWmain), [evX0] stage A ([evW2] before KV),
//         evA, [evXD] D: Qproj, KV 1-15, [evC] KV {0,16}, scores, softmax,
//         PV, O-proj
//   s2:   [evFork] wcvt2(Wk,Wv) (evW2), [evXB+evWmain] stage B, Qn,
//         [evA] stage C, [evXD] P1 patch, evC
// ---------------------------------------------------------------------------
#define Bn 8
#define Dn 1024
#define NP 2176
#define NS 640
#define MQ 2048

#define EL_XD ((size_t)Bn * NP * Dn)
#define EL_S  ((size_t)Bn * MQ * NP)
#define EL_XS ((size_t)Bn * NS * Dn)
#define EL_SS ((size_t)Bn * NS * NS)

__device__ __align__(256) __half g_X[EL_XD];
__device__ __align__(256) __half g_XD[EL_XD];
__device__ __align__(256) __half g_Q[EL_XD];
__device__ __align__(256) __half g_K[EL_XD];
__device__ __align__(256) __half g_Vt[EL_XD];
__device__ __align__(256) __half g_O[EL_XD];
__device__ __align__(256) __half g_P[EL_S];
__device__ __align__(256) float  g_S[EL_S];
// Stage B scratch
__device__ __align__(256) __half g_XB[EL_XS];
__device__ __align__(256) __half g_QB[EL_XS];
__device__ __align__(256) __half g_KB[EL_XS];
__device__ __align__(256) __half g_VtB[EL_XS];
__device__ __align__(256) __half g_OB[EL_XS];
__device__ __align__(256) __half g_PB[EL_SS];
__device__ __align__(256) float  g_SB[EL_SS];
// weights
__device__ __align__(256) __half g_WqT[Dn*Dn], g_WoT[Dn*Dn];
__device__ __align__(256) __half g_WkvT[2*Dn*Dn];
// stage C fp32 scratch (g_M1/g_S1 rows 8..127 never written -> stay zero)
__device__ __align__(256) float g_M1[128 * Dn];
__device__ __align__(256) float g_S1[128 * Dn];
__device__ __align__(256) float g_Qn[128 * Dn];
__device__ __align__(256) float g_Kp[128 * Dn];
__device__ __align__(256) float g_P1[Bn * Dn];

// ---------------------------------------------------------------------------
__device__ __forceinline__ uint32_t smem_u32(const void* p) {
    uint32_t a;
    asm("{ .reg .u64 t; cvta.to.shared.u64 t, %1; cvt.u32.u64 %0, t; }"
        : "=r"(a) : "l"(p));
    return a;
}
__device__ __forceinline__ uint32_t swz(int row, int col16) {
    return ((uint32_t)row << 7) | ((uint32_t)((col16 ^ row) & 7) << 4);
}
__device__ __forceinline__ void ldsm4(uint32_t* r, uint32_t addr) {
    asm volatile("ldmatrix.sync.aligned.m8n8.x4.shared.b16 {%0,%1,%2,%3}, [%4];"
        : "=r"(r[0]), "=r"(r[1]), "=r"(r[2]), "=r"(r[3]) : "r"(addr));
}
__device__ __forceinline__ void mma_f16(float* d, const uint32_t* a, const uint32_t* b) {
    asm volatile(
        "mma.sync.aligned.m16n8k16.row.col.f32.f16.f16.f32 "
        "{%0,%1,%2,%3}, {%4,%5,%6,%7}, {%8,%9}, {%0,%1,%2,%3};"
        : "+f"(d[0]), "+f"(d[1]), "+f"(d[2]), "+f"(d[3])
        : "r"(a[0]), "r"(a[1]), "r"(a[2]), "r"(a[3]), "r"(b[0]), "r"(b[1]));
}

// ---------------------------------------------------------------------------
// fp16 tensor-core GEMM. MODE 0/1/2/3/5. ytstep scales the M-tile stride of
// blockIdx.y (ytstep=16 + gridDim.y=2 covers row-tiles {0,16} in ONE launch).
// ---------------------------------------------------------------------------
#define STAGE_B 32768
#define TG_SMEM (3 * STAGE_B)

__device__ __forceinline__ void fill_chunk(uint32_t sm,
    const __half* A, const __half* Bm, int ldA, int ldB, int t, int c)
{
    long long k0 = (long long)c << 6;
#pragma unroll
    for (int i = 0; i < 4; i++) {
        int seg = t + (i << 8);
        int row = seg >> 3;
        int cc  = seg & 7;
        uint32_t so = swz(row, cc);
        asm volatile("cp.async.cg.shared.global [%0], [%1], 16;"
                     :: "r"(sm + so),
                        "l"(A + (long long)row * ldA + k0 + ((long long)cc << 3)));
        asm volatile("cp.async.cg.shared.global [%0], [%1], 16;"
                     :: "r"(sm + 16384u + so),
                        "l"(Bm + (long long)row * ldB + k0 + ((long long)cc << 3)));
    }
}

template <int MODE, bool BIAS>
__global__ void __launch_bounds__(256, 2)
tgemm(const __half* __restrict__ A, const __half* __restrict__ Bm,
      float* __restrict__ Cf, __half* __restrict__ Ch, __half* __restrict__ Ch2,
      const float* __restrict__ bias, const float* __restrict__ bias2,
      float* __restrict__ aux,
      int tokens, int mtok, int xsplit, int ytstep,
      int Kd, int ldA, int ldB, int ldc, int ldc2, float scale,
      long long sA, long long sB, long long sC)
{
    extern __shared__ __align__(1024) char smem[];
    const int tid = threadIdx.x, wid = tid >> 5, lane = tid & 31;
    const long long z = blockIdx.z;
    A += z * sA; Bm += z * sB;
    if (MODE == 0 || MODE == 3) Cf += z * sC;
    else { Ch += z * sC; if (MODE == 5) Ch2 += z * sC; }

    const uint32_t sb = smem_u32(smem);
    const int yt = blockIdx.y * ytstep;
    const __half* At = A  + (long long)yt * 128 * ldA;
    const __half* Bt = Bm + (long long)blockIdx.x * 128 * ldB;

    const int wr = wid >> 2, wc = wid & 3;
    const int m0 = wr * 64, n0 = wc * 32;

    float acc[4][4][4];
#pragma unroll
    for (int i = 0; i < 4; i++)
#pragma unroll
        for (int j = 0; j < 4; j++)
#pragma unroll
            for (int r = 0; r < 4; r++) acc[i][j][r] = 0.f;

    const int NC = Kd >> 6;
    fill_chunk(sb, At, Bt, ldA, ldB, tid, 0);
    asm volatile("cp.async.commit_group;");
    if (NC > 1) {
        fill_chunk(sb + STAGE_B, At, Bt, ldA, ldB, tid, 1);
        asm volatile("cp.async.commit_group;");
    }

#pragma unroll 1
    for (int c = 0; c < NC; c++) {
        if (c == NC - 1) asm volatile("cp.async.wait_group 0;");
        else             asm volatile("cp.async.wait_group 1;");
        __syncthreads();

        const uint32_t tb = sb + (uint32_t)(c % 3) * STAGE_B;
        const uint32_t aA = tb, aB = tb + 16384u;

#pragma unroll
        for (int kk = 0; kk < 4; kk++) {
            const int k16 = kk << 1;
            uint32_t Af[4][4], Bf[2][4];
            const int ar = m0 + (lane & 15);
            const int ac = k16 + (lane >> 4);
#pragma unroll
            for (int i = 0; i < 4; i++)
                ldsm4(Af[i], aA + swz(ar + 16 * i, ac));
            const int br = n0 + ((lane >> 4) << 3) + (lane & 7);
            const int bc = k16 + ((lane >> 3) & 1);
#pragma unroll
            for (int j2 = 0; j2 < 2; j2++)
                ldsm4(Bf[j2], aB + swz(br + 16 * j2, bc));
#pragma unroll
            for (int i = 0; i < 4; i++)
#pragma unroll
                for (int jt = 0; jt < 4; jt++)
                    mma_f16(acc[i][jt], Af[i], &Bf[jt >> 1][(jt & 1) << 1]);
        }
        if (c + 2 < NC) {
            fill_chunk(sb + (uint32_t)((c + 2) % 3) * STAGE_B, At, Bt, ldA, ldB,
                       tid, c + 2);
            asm volatile("cp.async.commit_group;");
        }
    }

    const int row0 = yt * 128, col0 = blockIdx.x * 128;
    const int rl = lane >> 2;
    const int cl = (lane & 3) << 1;
    const float* bp = bias;
    int cof = 0;
    bool vpath = false;
    if (MODE == 5 && col0 >= (xsplit << 7)) {
        bp = bias2;
        cof = xsplit << 7;
        vpath = true;
    }
#pragma unroll
    for (int i = 0; i < 4; i++) {
        const long long rg0 = row0 + m0 + i * 16 + rl;
        const long long rg1 = rg0 + 8;
#pragma unroll
        for (int j = 0; j < 4; j++) {
            const int cg = col0 + n0 + j * 8 + cl;
            float v00 = acc[i][j][0] * scale, v01 = acc[i][j][1] * scale;
            float v10 = acc[i][j][2] * scale, v11 = acc[i][j][3] * scale;
            if (BIAS) {
                const float b0 = bp[cg - cof], b1 = bp[cg - cof + 1];
                v00 += b0; v01 += b1; v10 += b0; v11 += b1;
            }
            if (MODE == 0) {
                *(float2*)(Cf + rg0 * ldc + cg) = make_float2(v00, v01);
                *(float2*)(Cf + rg1 * ldc + cg) = make_float2(v10, v11);
            } else if (MODE == 1) {
                *(__half2*)(Ch + rg0 * ldc + cg) =
                    __halves2half2(__float2half_rn(v00), __float2half_rn(v01));
                *(__half2*)(Ch + rg1 * ldc + cg) =
                    __halves2half2(__float2half_rn(v10), __float2half_rn(v11));
            } else if (MODE == 2) {
                Ch[(long long)cg * ldc + rg0]       = __float2half_rn(v00);
                Ch[(long long)(cg + 1) * ldc + rg0] = __float2half_rn(v01);
                Ch[(long long)cg * ldc + rg1]       = __float2half_rn(v10);
                Ch[(long long)(cg + 1) * ldc + rg1] = __float2half_rn(v11);
            } else if (MODE == 3) {
                const int r0 = (int)rg0, r1 = (int)rg1;
                if (r0 < tokens)
                    *(float2*)(Cf + (long long)r0 * ldc + cg) =
                        make_float2(v00, v01);
                if (r0 == mtok)
                    *(float2*)(aux + z * 1024 + cg) = make_float2(v00, v01);
                if (r1 < tokens)
                    *(float2*)(Cf + (long long)r1 * ldc + cg) =
                        make_float2(v10, v11);
                if (r1 == mtok)
                    *(float2*)(aux + z * 1024 + cg) = make_float2(v10, v11);
            } else { // MODE 5
                if (!vpath) {
                    *(__half2*)(Ch + rg0 * ldc + cg) =
                        __halves2half2(__float2half_rn(v00), __float2half_rn(v01));
                    *(__half2*)(Ch + rg1 * ldc + cg) =
                        __halves2half2(__float2half_rn(v10), __float2half_rn(v11));
                } else {
                    const int vc = cg - cof;
                    Ch2[(long long)vc * ldc2 + rg0]       = __float2half_rn(v00);
                    Ch2[(long long)(vc + 1) * ldc2 + rg0] = __float2half_rn(v01);
                    Ch2[(long long)vc * ldc2 + rg1]       = __float2half_rn(v10);
                    Ch2[(long long)(vc + 1) * ldc2 + rg1] = __float2half_rn(v11);
                }
            }
        }
    }
}

// ---------------------------------------------------------------------------
__global__ void softmax_reg(const float* __restrict__ S, __half* __restrict__ P,
                            int n, int npad, int rowsPB, int row0)
{
    const long long roff =
        ((long long)blockIdx.y * rowsPB + (row0 + blockIdx.x)) * npad;
    const float4* row4 = (const float4*)(S + roff);
    __half* pr = P + roff;
    const int t = threadIdx.x;
    const int npad4 = npad >> 2;
    __shared__ float red[256];

    float4 v[3];
    float m = -1e30f;
#pragma unroll
    for (int p = 0; p < 3; p++) {
        const int i4 = t + (p << 8);
        if (i4 < npad4) {
            v[p] = row4[i4];
            const int j = i4 << 2;
            if (j + 0 < n) m = fmaxf(m, v[p].x);
            if (j + 1 < n) m = fmaxf(m, v[p].y);
            if (j + 2 < n) m = fmaxf(m, v[p].z);
            if (j + 3 < n) m = fmaxf(m, v[p].w);
        }
    }
    red[t] = m; __syncthreads();
    for (int s = 128; s > 0; s >>= 1) {
        if (t < s) red[t] = fmaxf(red[t], red[t + s]);
        __syncthreads();
    }
    m = red[0]; __syncthreads();

    float sum = 0.f;
#pragma unroll
    for (int p = 0; p < 3; p++) {
        const int i4 = t + (p << 8);
        if (i4 < npad4) {
            const int j = i4 << 2;
            v[p].x = (j + 0 < n) ? __expf(v[p].x - m) : 0.f;
            v[p].y = (j + 1 < n) ? __expf(v[p].y - m) : 0.f;
            v[p].z = (j + 2 < n) ? __expf(v[p].z - m) : 0.f;
            v[p].w = (j + 3 < n) ? __expf(v[p].w - m) : 0.f;
            sum += v[p].x + v[p].y + v[p].z + v[p].w;
        }
    }
    red[t] = sum; __syncthreads();
    for (int s = 128; s > 0; s >>= 1) {
        if (t < s) red[t] += red[t + s];
        __syncthreads();
    }
    const float inv = 1.f / red[0];

#pragma unroll
    for (int p = 0; p < 3; p++) {
        const int i4 = t + (p << 8);
        if (i4 < npad4) {
            const int j = i4 << 2;
            *(__half2*)(pr + j)     = __halves2half2(__float2half_rn(v[p].x * inv),
                                                     __float2half_rn(v[p].y * inv));
            *(__half2*)(pr + j + 2) = __halves2half2(__float2half_rn(v[p].z * inv),
                                                     __float2half_rn(v[p].w * inv));
        }
    }
}

// ---------------------------------------------------------------------------
__global__ void build_x0h(const float* __restrict__ seg0, __half* __restrict__ X)
{
    int b = blockIdx.y;
    long long i2 = (long long)blockIdx.x * 256 + threadIdx.x;
    int pos = (int)(i2 >> 9), d = (int)((i2 & 511) << 1);
    float2 v = make_float2(0.f, 0.f);
    if (pos >= 1 && pos <= 2048)
        v = *(const float2*)(seg0 + ((long long)b * 2048 + (pos - 1)) * 1024 + d);
    *(__half2*)(X + (long long)b * NP * 1024 + (i2 << 1)) =
        __halves2half2(__float2half_rn(v.x), __float2half_rn(v.y));
}

__global__ void build_xsh(const float* __restrict__ seg1, const float* __restrict__ pe,
                          __half* __restrict__ X)
{
    int b = blockIdx.y;
    long long i2 = (long long)blockIdx.x * 256 + threadIdx.x;
    int pos = (int)(i2 >> 9), d = (int)((i2 & 511) << 1);
    float2 v = make_float2(0.f, 0.f);
    if (pos == 0 || pos == 513) v = *(const float2*)(pe + d);
    else if (pos >= 1 && pos <= 512)
        v = *(const float2*)(seg1 + ((long long)b * 2048 + (pos - 1)) * 1024 + d);
    *(__half2*)(X + (long long)b * NS * 1024 + (i2 << 1)) =
        __halves2half2(__float2half_rn(v.x), __float2half_rn(v.y));
}

__global__ void build_x1main(const float* __restrict__ seg0,
                             const float* __restrict__ seg1,
                             __half* __restrict__ X)
{
    int b = blockIdx.y;
    long long i2 = (long long)blockIdx.x * 256 + threadIdx.x;
    int pos = (int)(i2 >> 9), d = (int)((i2 & 511) << 1);
    float2 v = make_float2(0.f, 0.f);
    if (pos < 32)
        v = *(const float2*)(seg0 + ((long long)b * 2048 + (2016 + pos)) * 1024 + d);
    else if (pos >= 33 && pos <= 2080)
        v = *(const float2*)(seg1 + ((long long)b * 2048 + (pos - 33)) * 1024 + d);
    *(__half2*)(X + (long long)b * NP * 1024 + (i2 << 1)) =
        __halves2half2(__float2half_rn(v.x), __float2half_rn(v.y));
}

__global__ void build_x1_p1(const float* __restrict__ P1, __half* __restrict__ X)
{
    int i = blockIdx.x * 256 + threadIdx.x;
    int b = i >> 10;
    int rem = i & 1023;
    int pos = (rem >> 9) ? 2081 : 32;
    int d = (rem & 511) << 1;
    float2 v = *(const float2*)(P1 + b * 1024 + d);
    *(__half2*)(X + ((long long)b * NP + pos) * 1024 + d) =
        __halves2half2(__float2half_rn(v.x), __float2half_rn(v.y));
}

// merged weight transpose+convert for TWO weights: blockIdx.z selects pair
__global__ void wcvt2(const float* __restrict__ W0, __half* __restrict__ WT0,
                      const float* __restrict__ W1, __half* __restrict__ WT1)
{
    __shared__ float tile[32][33];
    const float* W = blockIdx.z ? W1 : W0;
    __half* WT     = blockIdx.z ? WT1 : WT0;
    const int k0 = blockIdx.y * 32, n0 = blockIdx.x * 32;
    for (int r = threadIdx.y; r < 32; r += 8)
        tile[r][threadIdx.x] = W[(long long)(k0 + r) * 1024 + n0 + threadIdx.x];
    __syncthreads();
    for (int r = threadIdx.y; r < 32; r += 8)
        WT[(long long)(n0 + r) * 1024 + k0 + threadIdx.x] =
            __float2half_rn(tile[threadIdx.x][r]);
}

// ---------------------------------------------------------------------------
template <bool TRANSB, bool BIAS>
__global__ void __launch_bounds__(256)
sgemm(const float* __restrict__ A, const float* __restrict__ Bm,
      float* __restrict__ C, const float* __restrict__ bias,
      int N, int Kd, float scale)
{
    __shared__ float As[8][128];
    __shared__ float Bs[8][128];
    const int t = threadIdx.x, tx = t & 15, ty = t >> 4;
    const int row0 = blockIdx.y * 128, col0 = blockIdx.x * 128;
    const int aRow = t >> 1, aCol = (t & 1) << 2;
    const int bRow = t >> 5, bCol = (t & 31) << 2;
    float acc[8][8];
#pragma unroll
    for (int i = 0; i < 8; i++)
#pragma unroll
        for (int j = 0; j < 8; j++) acc[i][j] = 0.f;
    const float* Aptr = A + (long long)(row0 + aRow) * Kd + aCol;
    const float* Bptr = TRANSB ? (Bm + (long long)(col0 + aRow) * Kd + aCol)
                               : (Bm + (long long)bRow * N + col0 + bCol);
    for (int k0 = 0; k0 < Kd; k0 += 8) {
        float4 av = *(const float4*)(Aptr + k0);
        As[aCol + 0][aRow] = av.x; As[aCol + 1][aRow] = av.y;
        As[aCol + 2][aRow] = av.z; As[aCol + 3][aRow] = av.w;
        if (TRANSB) {
            float4 bv = *(const float4*)(Bptr + k0);
            Bs[aCol + 0][aRow] = bv.x; Bs[aCol + 1][aRow] = bv.y;
            Bs[aCol + 2][aRow] = bv.z; Bs[aCol + 3][aRow] = bv.w;
        } else {
            float4 bv = *(const float4*)(Bptr + (long long)k0 * N);
            *(float4*)&Bs[bRow][bCol] = bv;
        }
        __syncthreads();
#pragma unroll
        for (int kk = 0; kk < 8; kk++) {
            float ar[8], br[8];
            *(float4*)&ar[0] = *(const float4*)&As[kk][ty * 8];
            *(float4*)&ar[4] = *(const float4*)&As[kk][ty * 8 + 4];
            *(float4*)&br[0] = *(const float4*)&Bs[kk][tx * 8];
            *(float4*)&br[4] = *(const float4*)&Bs[kk][tx * 8 + 4];
#pragma unroll
            for (int i = 0; i < 8; i++)
#pragma unroll
                for (int j = 0; j < 8; j++)
                    acc[i][j] = fmaf(ar[i], br[j], acc[i][j]);
        }
        __syncthreads();
    }
#pragma unroll
    for (int i = 0; i < 8; i++) {
        long long r = row0 + ty * 8 + i;
#pragma unroll
        for (int j = 0; j < 8; j += 4) {
            int c = col0 + tx * 8 + j;
            float4 v;
            v.x = acc[i][j + 0] * scale; v.y = acc[i][j + 1] * scale;
            v.z = acc[i][j + 2] * scale; v.w = acc[i][j + 3] * scale;
            if (BIAS) { v.x += bias[c]; v.y += bias[c + 1]; v.z += bias[c + 2]; v.w += bias[c + 3]; }
            *(float4*)(C + r * N + c) = v;
        }
    }
}

__global__ void mem_attn(const float* __restrict__ Qn, const float* __restrict__ Kp,
                         const float* __restrict__ M1, float* __restrict__ P1)
{
    int b = blockIdx.x, t = threadIdx.x;
    __shared__ float red[256];
    __shared__ float attn[Bn];
    for (int j = 0; j < Bn; j++) {
        float p = 0.f;
        for (int d = t; d < 1024; d += 256)
            p += Qn[b * 1024 + d] * Kp[j * 1024 + d];
        red[t] = p; __syncthreads();
        for (int s = 128; s > 0; s >>= 1) {
            if (t < s) red[t] += red[t + s];
            __syncthreads();
        }
        if (t == 0) attn[j] = red[0] * 0.03125f;
        __syncthreads();
    }
    if (t == 0) {
        float m = -1e30f;
        for (int j = 0; j < Bn; j++) m = fmaxf(m, attn[j]);
        float s = 0.f;
        for (int j = 0; j < Bn; j++) { attn[j] = __expf(attn[j] - m); s += attn[j]; }
        float inv = 1.f / s;
        for (int j = 0; j < Bn; j++) attn[j] *= inv;
    }
    __syncthreads();
    for (int d = t; d < 1024; d += 256) {
        float v = 0.f;
#pragma unroll
        for (int j = 0; j < Bn; j++) v += attn[j] * M1[j * 1024 + d];
        P1[b * 1024 + d] = v;
    }
}

// ---------------------------------------------------------------------------
extern "C" void kernel_launch(void* const* d_in, const int* in_sizes, int n_in,
                              void* d_out, int out_size)
{
    const float* seg0   = (const float*)d_in[0];
    const float* seg1   = (const float*)d_in[1];
    const float* pe     = (const float*)d_in[2];
    const float* Wq_mem = (const float*)d_in[3];
    const float* bq_mem = (const float*)d_in[4];
    const float* Wk_mem = (const float*)d_in[5];
    const float* bk_mem = (const float*)d_in[6];
    const float* Wq     = (const float*)d_in[7];
    const float* bq     = (const float*)d_in[8];
    const float* Wk     = (const float*)d_in[9];
    const float* bk     = (const float*)d_in[10];
    const float* Wv     = (const float*)d_in[11];
    const float* bv     = (const float*)d_in[12];
    const float* Wo     = (const float*)d_in[13];
    const float* bo     = (const float*)d_in[14];
    float* out = (float*)d_out;

    static cudaStream_t s2 = nullptr, s3 = nullptr;
    static cudaEvent_t evFork = nullptr, evWmain = nullptr, evW2 = nullptr,
                       evX0 = nullptr, evXB = nullptr, evXD = nullptr,
                       evA = nullptr, evC = nullptr;
    if (s2 == nullptr) {
        cudaStreamCreateWithFlags(&s2, cudaStreamNonBlocking);
        cudaStreamCreateWithFlags(&s3, cudaStreamNonBlocking);
        cudaEventCreateWithFlags(&evFork, cudaEventDisableTiming);
        cudaEventCreateWithFlags(&evWmain, cudaEventDisableTiming);
        cudaEventCreateWithFlags(&evW2, cudaEventDisableTiming);
        cudaEventCreateWithFlags(&evX0, cudaEventDisableTiming);
        cudaEventCreateWithFlags(&evXB, cudaEventDisableTiming);
        cudaEventCreateWithFlags(&evXD, cudaEventDisableTiming);
        cudaEventCreateWithFlags(&evA, cudaEventDisableTiming);
        cudaEventCreateWithFlags(&evC, cudaEventDisableTiming);
        cudaFuncSetAttribute(tgemm<0, false>, cudaFuncAttributeMaxDynamicSharedMemorySize, TG_SMEM);
        cudaFuncSetAttribute(tgemm<1, false>, cudaFuncAttributeMaxDynamicSharedMemorySize, TG_SMEM);
        cudaFuncSetAttribute(tgemm<1, true>,  cudaFuncAttributeMaxDynamicSharedMemorySize, TG_SMEM);
        cudaFuncSetAttribute(tgemm<3, true>,  cudaFuncAttributeMaxDynamicSharedMemorySize, TG_SMEM);
        cudaFuncSetAttribute(tgemm<5, true>,  cudaFuncAttributeMaxDynamicSharedMemorySize, TG_SMEM);
    }

    __half *pX, *pXD, *pQ, *pK, *pVt, *pO, *pP;
    __half *pXB, *pQB, *pKB, *pVtB, *pOB, *pPB;
    __half *pWqT, *pWoT, *pWkvT;
    float *pS, *pSB, *pM1, *pS1, *pQn, *pKp, *pP1;
    cudaGetSymbolAddress((void**)&pX, g_X);
    cudaGetSymbolAddress((void**)&pXD, g_XD);
    cudaGetSymbolAddress((void**)&pQ, g_Q);
    cudaGetSymbolAddress((void**)&pK, g_K);
    cudaGetSymbolAddress((void**)&pVt, g_Vt);
    cudaGetSymbolAddress((void**)&pO, g_O);
    cudaGetSymbolAddress((void**)&pP, g_P);
    cudaGetSymbolAddress((void**)&pXB, g_XB);
    cudaGetSymbolAddress((void**)&pQB, g_QB);
    cudaGetSymbolAddress((void**)&pKB, g_KB);
    cudaGetSymbolAddress((void**)&pVtB, g_VtB);
    cudaGetSymbolAddress((void**)&pOB, g_OB);
    cudaGetSymbolAddress((void**)&pPB, g_PB);
    cudaGetSymbolAddress((void**)&pWqT, g_WqT);
    cudaGetSymbolAddress((void**)&pWoT, g_WoT);
    cudaGetSymbolAddress((void**)&pWkvT, g_WkvT);
    cudaGetSymbolAddress((void**)&pS, g_S);
    cudaGetSymbolAddress((void**)&pSB, g_SB);
    cudaGetSymbolAddress((void**)&pM1, g_M1);
    cudaGetSymbolAddress((void**)&pS1, g_S1);
    cudaGetSymbolAddress((void**)&pQn, g_Qn);
    cudaGetSymbolAddress((void**)&pKp, g_Kp);
    cudaGetSymbolAddress((void**)&pP1, g_P1);

    const long long sXD = (long long)NP * Dn;
    const long long sS  = (long long)MQ * NP;
    const long long sXB = (long long)NS * Dn;
    const long long sSB = (long long)NS * NS;

    // ---- FORK at the very start ----
    cudaEventRecord(evFork, 0);
    cudaStreamWaitEvent(s2, evFork, 0);
    cudaStreamWaitEvent(s3, evFork, 0);

    // s3: all input builds (memory-bound; co-run with weight conversions)
    build_x0h<<<dim3(NP * Dn / 512, Bn), 256, 0, s3>>>(seg0, pX);
    cudaEventRecord(evX0, s3);
    build_xsh<<<dim3(NS * Dn / 512, Bn), 256, 0, s3>>>(seg1, pe, pXB);
    cudaEventRecord(evXB, s3);
    build_x1main<<<dim3(NP * Dn / 512, Bn), 256, 0, s3>>>(seg0, seg1, pXD);
    cudaEventRecord(evXD, s3);

    // main: Wq + Wo in one launch
    dim3 wb(32, 8);
    wcvt2<<<dim3(32, 32, 2), wb>>>(Wq, pWqT, Wo, pWoT);
    cudaEventRecord(evWmain, 0);
    // s2: Wk + Wv in one launch (into the concatenated KV weight buffer)
    wcvt2<<<dim3(32, 32, 2), wb, 0, s2>>>(Wk, pWkvT, Wv, pWkvT + (size_t)Dn * Dn);
    cudaEventRecord(evW2, s2);

    // === s2: stage B, Qn ===
    cudaStreamWaitEvent(s2, evXB, 0);
    tgemm<5, true><<<dim3(16, 5, Bn), 256, TG_SMEM, s2>>>(pXB, pWkvT,
        nullptr, pKB, pVtB, bk, bv, nullptr, 0, -1, 8, 1,
        Dn, Dn, Dn, Dn, NS, 1.f, sXB, 0, sXB);
    cudaStreamWaitEvent(s2, evWmain, 0);   // WqT/WoT ready for B's Q/O proj
    tgemm<1, true><<<dim3(8, 1, Bn), 256, TG_SMEM, s2>>>(pXB + 512 * Dn, pWqT,
        nullptr, pQB + 512 * Dn, nullptr, bq, nullptr, nullptr, 0, -1, 0, 1,
        Dn, Dn, Dn, Dn, 0, 1.f, sXB, 0, sXB);
    tgemm<0, false><<<dim3(5, 1, Bn), 256, TG_SMEM, s2>>>(pQB + 512 * Dn, pKB,
        pSB + 512 * NS, nullptr, nullptr, nullptr, nullptr, nullptr, 0, -1, 0, 1,
        Dn, Dn, Dn, NS, 0, 0.03125f, sXB, sXB, sSB);
    softmax_reg<<<dim3(128, Bn), 256, 0, s2>>>(pSB, pPB, 514, NS, NS, 512);
    tgemm<1, false><<<dim3(8, 1, Bn), 256, TG_SMEM, s2>>>(pPB + 512 * NS, pVtB,
        nullptr, pOB + 512 * Dn, nullptr, nullptr, nullptr, nullptr, 0, -1, 0, 1,
        576, NS, NS, Dn, 0, 1.f, sSB, sXB, sXB);
    tgemm<3, true><<<dim3(8, 1, Bn), 256, TG_SMEM, s2>>>(pOB + 512 * Dn, pWoT,
        out, nullptr, nullptr, bo, nullptr, pS1, 0, 0, 0, 1,
        Dn, Dn, Dn, Dn, 0, 1.f, sXB, 0, 0);
    sgemm<false, true><<<dim3(Dn / 128, 1), 256, 0, s2>>>(pS1, Wq_mem, pQn,
                                                          bq_mem, Dn, Dn, 1.f);

    // === main: stage A ===
    cudaStreamWaitEvent(0, evX0, 0);
    {
        const int n = 2050, KT = 2112;
        tgemm<1, true><<<dim3(8, 16, Bn), 256, TG_SMEM>>>(pX + 33 * Dn, pWqT,
            nullptr, pQ, nullptr, bq, nullptr, nullptr, 0, -1, 0, 1,
            Dn, Dn, Dn, Dn, 0, 1.f, sXD, 0, sXD);
        cudaStreamWaitEvent(0, evW2, 0);   // WkvT ready
        tgemm<5, true><<<dim3(16, 17, Bn), 256, TG_SMEM>>>(pX, pWkvT,
            nullptr, pK, pVt, bk, bv, nullptr, 0, -1, 8, 1,
            Dn, Dn, Dn, Dn, NP, 1.f, sXD, 0, sXD);
        tgemm<0, false><<<dim3(17, 16, Bn), 256, TG_SMEM>>>(pQ, pK, pS,
            nullptr, nullptr, nullptr, nullptr, nullptr, 0, -1, 0, 1,
            Dn, Dn, Dn, NP, 0, 0.03125f, sXD, sXD, sS);
        softmax_reg<<<dim3(MQ, Bn), 256>>>(pS, pP, n, NP, MQ, 0);
        tgemm<1, false><<<dim3(8, 16, Bn), 256, TG_SMEM>>>(pP, pVt,
            nullptr, pO, nullptr, nullptr, nullptr, nullptr, 0, -1, 0, 1,
            KT, NP, NP, Dn, 0, 1.f, sS, sXD, sXD);
        tgemm<3, true><<<dim3(8, 16, Bn), 256, TG_SMEM>>>(pO, pWoT,
            out, nullptr, nullptr, bo, nullptr, pM1, 2016, 2016, 0, 1,
            Dn, Dn, Dn, Dn, 0, 1.f, sXD, 0, (long long)2016 * Dn);
    }
    cudaEventRecord(evA, 0);

    // === s2: stage C (needs M1 from A) + P1 patch into XD ===
    cudaStreamWaitEvent(s2, evA, 0);
    sgemm<false, true><<<dim3(Dn / 128, 1), 256, 0, s2>>>(pM1, Wk_mem, pKp,
                                                          bk_mem, Dn, Dn, 1.f);
    mem_attn<<<Bn, 256, 0, s2>>>(pQn, pKp, pM1, pP1);
    cudaStreamWaitEvent(s2, evXD, 0);      // XD built (long done)
    build_x1_p1<<<32, 256, 0, s2>>>(pP1, pXD);
    cudaEventRecord(evC, s2);

    // === main: stage D (P1-independent GEMMs overlap stage C) ===
    cudaStreamWaitEvent(0, evXD, 0);
    {
        const int n = 2082, KT = 2112;
        // Q projection: rows 33..2080, never touches P1 rows
        tgemm<1, true><<<dim3(8, 16, Bn), 256, TG_SMEM>>>(pXD + 33 * Dn, pWqT,
            nullptr, pQ, nullptr, bq, nullptr, nullptr, 0, -1, 0, 1,
            Dn, Dn, Dn, Dn, 0, 1.f, sXD, 0, sXD);
        // merged KV, row-tiles 1..15 (no P1 rows)
        tgemm<5, true><<<dim3(16, 15, Bn), 256, TG_SMEM>>>(pXD + 128 * Dn,
            pWkvT, nullptr, pK + 128 * Dn, pVt + 128, bk, bv, nullptr,
            0, -1, 8, 1, Dn, Dn, Dn, Dn, NP, 1.f, sXD, 0, sXD);
        // P1-dependent row-tiles 0 and 16 in ONE launch (ytstep=16)
        cudaStreamWaitEvent(0, evC, 0);
        tgemm<5, true><<<dim3(16, 2, Bn), 256, TG_SMEM>>>(pXD, pWkvT,
            nullptr, pK, pVt, bk, bv, nullptr, 0, -1, 8, 16,
            Dn, Dn, Dn, Dn, NP, 1.f, sXD, 0, sXD);
        tgemm<0, false><<<dim3(17, 16, Bn), 256, TG_SMEM>>>(pQ, pK, pS,
            nullptr, nullptr, nullptr, nullptr, nullptr, 0, -1, 0, 1,
            Dn, Dn, Dn, NP, 0, 0.03125f, sXD, sXD, sS);
        softmax_reg<<<dim3(MQ, Bn), 256>>>(pS, pP, n, NP, MQ, 0);
        tgemm<1, false><<<dim3(8, 16, Bn), 256, TG_SMEM>>>(pP, pVt,
            nullptr, pO, nullptr, nullptr, nullptr, nullptr, 0, -1, 0, 1,
            KT, NP, NP, Dn, 0, 1.f, sS, sXD, sXD);
        tgemm<3, true><<<dim3(8, 16, Bn), 256, TG_SMEM>>>(pO, pWoT,
            out + (long long)Bn * 2016 * Dn, nullptr, nullptr, bo, nullptr,
            pM1, 2048, -1, 0, 1, Dn, Dn, Dn, Dn, 0, 1.f, sXD, 0,
            (long long)2048 * Dn);
    }
}

// round 17
// speedup vs baseline: 1.0060x; 1.0060x over previous
#include <cuda_runtime.h>
#include <cuda_fp16.h>
#include <math.h>
#include <cstdint>

// ---------------------------------------------------------------------------
// B=8, L=2048, D=1024, K=32, J=512; n0=2050, ns=514, n1=2082
// NP=2176 (17*128), NS=640 (5*128). Queries offset 33 -> MQ=2048 rows.
// Schedule (= R15, the measured optimum, with merged wcvt2 from R16):
//   main: evFork, wcvt2(Wq,Wo), evWmain, build_x0h, stage A
//         [waits evW2 before A's KV], evA,
//         [wait evXD] D: Qproj, KV 1-15, [wait evC] KV {0,16} (one launch),
//         scores, softmax, PV, O-proj
//   s2:   [wait evFork] wcvt2(Wk,Wv), evW2, build XD, evXD, build XB,
//         B: KV, [wait evWmain] Qproj, scores, softmax, PV, O-proj->S1, Qn,
//         [wait evA] stage C, P1 patch, evC
// ---------------------------------------------------------------------------
#define Bn 8
#define Dn 1024
#define NP 2176
#define NS 640
#define MQ 2048

#define EL_XD ((size_t)Bn * NP * Dn)
#define EL_S  ((size_t)Bn * MQ * NP)
#define EL_XS ((size_t)Bn * NS * Dn)
#define EL_SS ((size_t)Bn * NS * NS)

__device__ __align__(256) __half g_X[EL_XD];
__device__ __align__(256) __half g_XD[EL_XD];
__device__ __align__(256) __half g_Q[EL_XD];
__device__ __align__(256) __half g_K[EL_XD];
__device__ __align__(256) __half g_Vt[EL_XD];
__device__ __align__(256) __half g_O[EL_XD];
__device__ __align__(256) __half g_P[EL_S];
__device__ __align__(256) float  g_S[EL_S];
// Stage B scratch
__device__ __align__(256) __half g_XB[EL_XS];
__device__ __align__(256) __half g_QB[EL_XS];
__device__ __align__(256) __half g_KB[EL_XS];
__device__ __align__(256) __half g_VtB[EL_XS];
__device__ __align__(256) __half g_OB[EL_XS];
__device__ __align__(256) __half g_PB[EL_SS];
__device__ __align__(256) float  g_SB[EL_SS];
// weights
__device__ __align__(256) __half g_WqT[Dn*Dn], g_WoT[Dn*Dn];
__device__ __align__(256) __half g_WkvT[2*Dn*Dn];
// stage C fp32 scratch (g_M1/g_S1 rows 8..127 never written -> stay zero)
__device__ __align__(256) float g_M1[128 * Dn];
__device__ __align__(256) float g_S1[128 * Dn];
__device__ __align__(256) float g_Qn[128 * Dn];
__device__ __align__(256) float g_Kp[128 * Dn];
__device__ __align__(256) float g_P1[Bn * Dn];

// ---------------------------------------------------------------------------
__device__ __forceinline__ uint32_t smem_u32(const void* p) {
    uint32_t a;
    asm("{ .reg .u64 t; cvta.to.shared.u64 t, %1; cvt.u32.u64 %0, t; }"
        : "=r"(a) : "l"(p));
    return a;
}
__device__ __forceinline__ uint32_t swz(int row, int col16) {
    return ((uint32_t)row << 7) | ((uint32_t)((col16 ^ row) & 7) << 4);
}
__device__ __forceinline__ void ldsm4(uint32_t* r, uint32_t addr) {
    asm volatile("ldmatrix.sync.aligned.m8n8.x4.shared.b16 {%0,%1,%2,%3}, [%4];"
        : "=r"(r[0]), "=r"(r[1]), "=r"(r[2]), "=r"(r[3]) : "r"(addr));
}
__device__ __forceinline__ void mma_f16(float* d, const uint32_t* a, const uint32_t* b) {
    asm volatile(
        "mma.sync.aligned.m16n8k16.row.col.f32.f16.f16.f32 "
        "{%0,%1,%2,%3}, {%4,%5,%6,%7}, {%8,%9}, {%0,%1,%2,%3};"
        : "+f"(d[0]), "+f"(d[1]), "+f"(d[2]), "+f"(d[3])
        : "r"(a[0]), "r"(a[1]), "r"(a[2]), "r"(a[3]), "r"(b[0]), "r"(b[1]));
}

// ---------------------------------------------------------------------------
// fp16 tensor-core GEMM. MODE 0/1/2/3/5. ytstep scales the M-tile stride of
// blockIdx.y (ytstep=16 + gridDim.y=2 covers row-tiles {0,16} in ONE launch).
// ---------------------------------------------------------------------------
#define STAGE_B 32768
#define TG_SMEM (3 * STAGE_B)

__device__ __forceinline__ void fill_chunk(uint32_t sm,
    const __half* A, const __half* Bm, int ldA, int ldB, int t, int c)
{
    long long k0 = (long long)c << 6;
#pragma unroll
    for (int i = 0; i < 4; i++) {
        int seg = t + (i << 8);
        int row = seg >> 3;
        int cc  = seg & 7;
        uint32_t so = swz(row, cc);
        asm volatile("cp.async.cg.shared.global [%0], [%1], 16;"
                     :: "r"(sm + so),
                        "l"(A + (long long)row * ldA + k0 + ((long long)cc << 3)));
        asm volatile("cp.async.cg.shared.global [%0], [%1], 16;"
                     :: "r"(sm + 16384u + so),
                        "l"(Bm + (long long)row * ldB + k0 + ((long long)cc << 3)));
    }
}

template <int MODE, bool BIAS>
__global__ void __launch_bounds__(256, 2)
tgemm(const __half* __restrict__ A, const __half* __restrict__ Bm,
      float* __restrict__ Cf, __half* __restrict__ Ch, __half* __restrict__ Ch2,
      const float* __restrict__ bias, const float* __restrict__ bias2,
      float* __restrict__ aux,
      int tokens, int mtok, int xsplit, int ytstep,
      int Kd, int ldA, int ldB, int ldc, int ldc2, float scale,
      long long sA, long long sB, long long sC)
{
    extern __shared__ __align__(1024) char smem[];
    const int tid = threadIdx.x, wid = tid >> 5, lane = tid & 31;
    const long long z = blockIdx.z;
    A += z * sA; Bm += z * sB;
    if (MODE == 0 || MODE == 3) Cf += z * sC;
    else { Ch += z * sC; if (MODE == 5) Ch2 += z * sC; }

    const uint32_t sb = smem_u32(smem);
    const int yt = blockIdx.y * ytstep;
    const __half* At = A  + (long long)yt * 128 * ldA;
    const __half* Bt = Bm + (long long)blockIdx.x * 128 * ldB;

    const int wr = wid >> 2, wc = wid & 3;
    const int m0 = wr * 64, n0 = wc * 32;

    float acc[4][4][4];
#pragma unroll
    for (int i = 0; i < 4; i++)
#pragma unroll
        for (int j = 0; j < 4; j++)
#pragma unroll
            for (int r = 0; r < 4; r++) acc[i][j][r] = 0.f;

    const int NC = Kd >> 6;
    fill_chunk(sb, At, Bt, ldA, ldB, tid, 0);
    asm volatile("cp.async.commit_group;");
    if (NC > 1) {
        fill_chunk(sb + STAGE_B, At, Bt, ldA, ldB, tid, 1);
        asm volatile("cp.async.commit_group;");
    }

#pragma unroll 1
    for (int c = 0; c < NC; c++) {
        if (c == NC - 1) asm volatile("cp.async.wait_group 0;");
        else             asm volatile("cp.async.wait_group 1;");
        __syncthreads();

        const uint32_t tb = sb + (uint32_t)(c % 3) * STAGE_B;
        const uint32_t aA = tb, aB = tb + 16384u;

#pragma unroll
        for (int kk = 0; kk < 4; kk++) {
            const int k16 = kk << 1;
            uint32_t Af[4][4], Bf[2][4];
            const int ar = m0 + (lane & 15);
            const int ac = k16 + (lane >> 4);
#pragma unroll
            for (int i = 0; i < 4; i++)
                ldsm4(Af[i], aA + swz(ar + 16 * i, ac));
            const int br = n0 + ((lane >> 4) << 3) + (lane & 7);
            const int bc = k16 + ((lane >> 3) & 1);
#pragma unroll
            for (int j2 = 0; j2 < 2; j2++)
                ldsm4(Bf[j2], aB + swz(br + 16 * j2, bc));
#pragma unroll
            for (int i = 0; i < 4; i++)
#pragma unroll
                for (int jt = 0; jt < 4; jt++)
                    mma_f16(acc[i][jt], Af[i], &Bf[jt >> 1][(jt & 1) << 1]);
        }
        if (c + 2 < NC) {
            fill_chunk(sb + (uint32_t)((c + 2) % 3) * STAGE_B, At, Bt, ldA, ldB,
                       tid, c + 2);
            asm volatile("cp.async.commit_group;");
        }
    }

    const int row0 = yt * 128, col0 = blockIdx.x * 128;
    const int rl = lane >> 2;
    const int cl = (lane & 3) << 1;
    const float* bp = bias;
    int cof = 0;
    bool vpath = false;
    if (MODE == 5 && col0 >= (xsplit << 7)) {
        bp = bias2;
        cof = xsplit << 7;
        vpath = true;
    }
#pragma unroll
    for (int i = 0; i < 4; i++) {
        const long long rg0 = row0 + m0 + i * 16 + rl;
        const long long rg1 = rg0 + 8;
#pragma unroll
        for (int j = 0; j < 4; j++) {
            const int cg = col0 + n0 + j * 8 + cl;
            float v00 = acc[i][j][0] * scale, v01 = acc[i][j][1] * scale;
            float v10 = acc[i][j][2] * scale, v11 = acc[i][j][3] * scale;
            if (BIAS) {
                const float b0 = bp[cg - cof], b1 = bp[cg - cof + 1];
                v00 += b0; v01 += b1; v10 += b0; v11 += b1;
            }
            if (MODE == 0) {
                *(float2*)(Cf + rg0 * ldc + cg) = make_float2(v00, v01);
                *(float2*)(Cf + rg1 * ldc + cg) = make_float2(v10, v11);
            } else if (MODE == 1) {
                *(__half2*)(Ch + rg0 * ldc + cg) =
                    __halves2half2(__float2half_rn(v00), __float2half_rn(v01));
                *(__half2*)(Ch + rg1 * ldc + cg) =
                    __halves2half2(__float2half_rn(v10), __float2half_rn(v11));
            } else if (MODE == 2) {
                Ch[(long long)cg * ldc + rg0]       = __float2half_rn(v00);
                Ch[(long long)(cg + 1) * ldc + rg0] = __float2half_rn(v01);
                Ch[(long long)cg * ldc + rg1]       = __float2half_rn(v10);
                Ch[(long long)(cg + 1) * ldc + rg1] = __float2half_rn(v11);
            } else if (MODE == 3) {
                const int r0 = (int)rg0, r1 = (int)rg1;
                if (r0 < tokens)
                    *(float2*)(Cf + (long long)r0 * ldc + cg) =
                        make_float2(v00, v01);
                if (r0 == mtok)
                    *(float2*)(aux + z * 1024 + cg) = make_float2(v00, v01);
                if (r1 < tokens)
                    *(float2*)(Cf + (long long)r1 * ldc + cg) =
                        make_float2(v10, v11);
                if (r1 == mtok)
                    *(float2*)(aux + z * 1024 + cg) = make_float2(v10, v11);
            } else { // MODE 5
                if (!vpath) {
                    *(__half2*)(Ch + rg0 * ldc + cg) =
                        __halves2half2(__float2half_rn(v00), __float2half_rn(v01));
                    *(__half2*)(Ch + rg1 * ldc + cg) =
                        __halves2half2(__float2half_rn(v10), __float2half_rn(v11));
                } else {
                    const int vc = cg - cof;
                    Ch2[(long long)vc * ldc2 + rg0]       = __float2half_rn(v00);
                    Ch2[(long long)(vc + 1) * ldc2 + rg0] = __float2half_rn(v01);
                    Ch2[(long long)vc * ldc2 + rg1]       = __float2half_rn(v10);
                    Ch2[(long long)(vc + 1) * ldc2 + rg1] = __float2half_rn(v11);
                }
            }
        }
    }
}

// ---------------------------------------------------------------------------
__global__ void softmax_reg(const float* __restrict__ S, __half* __restrict__ P,
                            int n, int npad, int rowsPB, int row0)
{
    const long long roff =
        ((long long)blockIdx.y * rowsPB + (row0 + blockIdx.x)) * npad;
    const float4* row4 = (const float4*)(S + roff);
    __half* pr = P + roff;
    const int t = threadIdx.x;
    const int npad4 = npad >> 2;
    __shared__ float red[256];

    float4 v[3];
    float m = -1e30f;
#pragma unroll
    for (int p = 0; p < 3; p++) {
        const int i4 = t + (p << 8);
        if (i4 < npad4) {
            v[p] = row4[i4];
            const int j = i4 << 2;
            if (j + 0 < n) m = fmaxf(m, v[p].x);
            if (j + 1 < n) m = fmaxf(m, v[p].y);
            if (j + 2 < n) m = fmaxf(m, v[p].z);
            if (j + 3 < n) m = fmaxf(m, v[p].w);
        }
    }
    red[t] = m; __syncthreads();
    for (int s = 128; s > 0; s >>= 1) {
        if (t < s) red[t] = fmaxf(red[t], red[t + s]);
        __syncthreads();
    }
    m = red[0]; __syncthreads();

    float sum = 0.f;
#pragma unroll
    for (int p = 0; p < 3; p++) {
        const int i4 = t + (p << 8);
        if (i4 < npad4) {
            const int j = i4 << 2;
            v[p].x = (j + 0 < n) ? __expf(v[p].x - m) : 0.f;
            v[p].y = (j + 1 < n) ? __expf(v[p].y - m) : 0.f;
            v[p].z = (j + 2 < n) ? __expf(v[p].z - m) : 0.f;
            v[p].w = (j + 3 < n) ? __expf(v[p].w - m) : 0.f;
            sum += v[p].x + v[p].y + v[p].z + v[p].w;
        }
    }
    red[t] = sum; __syncthreads();
    for (int s = 128; s > 0; s >>= 1) {
        if (t < s) red[t] += red[t + s];
        __syncthreads();
    }
    const float inv = 1.f / red[0];

#pragma unroll
    for (int p = 0; p < 3; p++) {
        const int i4 = t + (p << 8);
        if (i4 < npad4) {
            const int j = i4 << 2;
            *(__half2*)(pr + j)     = __halves2half2(__float2half_rn(v[p].x * inv),
                                                     __float2half_rn(v[p].y * inv));
            *(__half2*)(pr + j + 2) = __halves2half2(__float2half_rn(v[p].z * inv),
                                                     __float2half_rn(v[p].w * inv));
        }
    }
}

// ---------------------------------------------------------------------------
__global__ void build_x0h(const float* __restrict__ seg0, __half* __restrict__ X)
{
    int b = blockIdx.y;
    long long i2 = (long long)blockIdx.x * 256 + threadIdx.x;
    int pos = (int)(i2 >> 9), d = (int)((i2 & 511) << 1);
    float2 v = make_float2(0.f, 0.f);
    if (pos >= 1 && pos <= 2048)
        v = *(const float2*)(seg0 + ((long long)b * 2048 + (pos - 1)) * 1024 + d);
    *(__half2*)(X + (long long)b * NP * 1024 + (i2 << 1)) =
        __halves2half2(__float2half_rn(v.x), __float2half_rn(v.y));
}

__global__ void build_xsh(const float* __restrict__ seg1, const float* __restrict__ pe,
                          __half* __restrict__ X)
{
    int b = blockIdx.y;
    long long i2 = (long long)blockIdx.x * 256 + threadIdx.x;
    int pos = (int)(i2 >> 9), d = (int)((i2 & 511) << 1);
    float2 v = make_float2(0.f, 0.f);
    if (pos == 0 || pos == 513) v = *(const float2*)(pe + d);
    else if (pos >= 1 && pos <= 512)
        v = *(const float2*)(seg1 + ((long long)b * 2048 + (pos - 1)) * 1024 + d);
    *(__half2*)(X + (long long)b * NS * 1024 + (i2 << 1)) =
        __halves2half2(__float2half_rn(v.x), __float2half_rn(v.y));
}

__global__ void build_x1main(const float* __restrict__ seg0,
                             const float* __restrict__ seg1,
                             __half* __restrict__ X)
{
    int b = blockIdx.y;
    long long i2 = (long long)blockIdx.x * 256 + threadIdx.x;
    int pos = (int)(i2 >> 9), d = (int)((i2 & 511) << 1);
    float2 v = make_float2(0.f, 0.f);
    if (pos < 32)
        v = *(const float2*)(seg0 + ((long long)b * 2048 + (2016 + pos)) * 1024 + d);
    else if (pos >= 33 && pos <= 2080)
        v = *(const float2*)(seg1 + ((long long)b * 2048 + (pos - 33)) * 1024 + d);
    *(__half2*)(X + (long long)b * NP * 1024 + (i2 << 1)) =
        __halves2half2(__float2half_rn(v.x), __float2half_rn(v.y));
}

__global__ void build_x1_p1(const float* __restrict__ P1, __half* __restrict__ X)
{
    int i = blockIdx.x * 256 + threadIdx.x;
    int b = i >> 10;
    int rem = i & 1023;
    int pos = (rem >> 9) ? 2081 : 32;
    int d = (rem & 511) << 1;
    float2 v = *(const float2*)(P1 + b * 1024 + d);
    *(__half2*)(X + ((long long)b * NP + pos) * 1024 + d) =
        __halves2half2(__float2half_rn(v.x), __float2half_rn(v.y));
}

// merged weight transpose+convert for TWO weights: blockIdx.z selects pair
__global__ void wcvt2(const float* __restrict__ W0, __half* __restrict__ WT0,
                      const float* __restrict__ W1, __half* __restrict__ WT1)
{
    __shared__ float tile[32][33];
    const float* W = blockIdx.z ? W1 : W0;
    __half* WT     = blockIdx.z ? WT1 : WT0;
    const int k0 = blockIdx.y * 32, n0 = blockIdx.x * 32;
    for (int r = threadIdx.y; r < 32; r += 8)
        tile[r][threadIdx.x] = W[(long long)(k0 + r) * 1024 + n0 + threadIdx.x];
    __syncthreads();
    for (int r = threadIdx.y; r < 32; r += 8)
        WT[(long long)(n0 + r) * 1024 + k0 + threadIdx.x] =
            __float2half_rn(tile[threadIdx.x][r]);
}

// ---------------------------------------------------------------------------
template <bool TRANSB, bool BIAS>
__global__ void __launch_bounds__(256)
sgemm(const float* __restrict__ A, const float* __restrict__ Bm,
      float* __restrict__ C, const float* __restrict__ bias,
      int N, int Kd, float scale)
{
    __shared__ float As[8][128];
    __shared__ float Bs[8][128];
    const int t = threadIdx.x, tx = t & 15, ty = t >> 4;
    const int row0 = blockIdx.y * 128, col0 = blockIdx.x * 128;
    const int aRow = t >> 1, aCol = (t & 1) << 2;
    const int bRow = t >> 5, bCol = (t & 31) << 2;
    float acc[8][8];
#pragma unroll
    for (int i = 0; i < 8; i++)
#pragma unroll
        for (int j = 0; j < 8; j++) acc[i][j] = 0.f;
    const float* Aptr = A + (long long)(row0 + aRow) * Kd + aCol;
    const float* Bptr = TRANSB ? (Bm + (long long)(col0 + aRow) * Kd + aCol)
                               : (Bm + (long long)bRow * N + col0 + bCol);
    for (int k0 = 0; k0 < Kd; k0 += 8) {
        float4 av = *(const float4*)(Aptr + k0);
        As[aCol + 0][aRow] = av.x; As[aCol + 1][aRow] = av.y;
        As[aCol + 2][aRow] = av.z; As[aCol + 3][aRow] = av.w;
        if (TRANSB) {
            float4 bv = *(const float4*)(Bptr + k0);
            Bs[aCol + 0][aRow] = bv.x; Bs[aCol + 1][aRow] = bv.y;
            Bs[aCol + 2][aRow] = bv.z; Bs[aCol + 3][aRow] = bv.w;
        } else {
            float4 bv = *(const float4*)(Bptr + (long long)k0 * N);
            *(float4*)&Bs[bRow][bCol] = bv;
        }
        __syncthreads();
#pragma unroll
        for (int kk = 0; kk < 8; kk++) {
            float ar[8], br[8];
            *(float4*)&ar[0] = *(const float4*)&As[kk][ty * 8];
            *(float4*)&ar[4] = *(const float4*)&As[kk][ty * 8 + 4];
            *(float4*)&br[0] = *(const float4*)&Bs[kk][tx * 8];
            *(float4*)&br[4] = *(const float4*)&Bs[kk][tx * 8 + 4];
#pragma unroll
            for (int i = 0; i < 8; i++)
#pragma unroll
                for (int j = 0; j < 8; j++)
                    acc[i][j] = fmaf(ar[i], br[j], acc[i][j]);
        }
        __syncthreads();
    }
#pragma unroll
    for (int i = 0; i < 8; i++) {
        long long r = row0 + ty * 8 + i;
#pragma unroll
        for (int j = 0; j < 8; j += 4) {
            int c = col0 + tx * 8 + j;
            float4 v;
            v.x = acc[i][j + 0] * scale; v.y = acc[i][j + 1] * scale;
            v.z = acc[i][j + 2] * scale; v.w = acc[i][j + 3] * scale;
            if (BIAS) { v.x += bias[c]; v.y += bias[c + 1]; v.z += bias[c + 2]; v.w += bias[c + 3]; }
            *(float4*)(C + r * N + c) = v;
        }
    }
}

__global__ void mem_attn(const float* __restrict__ Qn, const float* __restrict__ Kp,
                         const float* __restrict__ M1, float* __restrict__ P1)
{
    int b = blockIdx.x, t = threadIdx.x;
    __shared__ float red[256];
    __shared__ float attn[Bn];
    for (int j = 0; j < Bn; j++) {
        float p = 0.f;
        for (int d = t; d < 1024; d += 256)
            p += Qn[b * 1024 + d] * Kp[j * 1024 + d];
        red[t] = p; __syncthreads();
        for (int s = 128; s > 0; s >>= 1) {
            if (t < s) red[t] += red[t + s];
            __syncthreads();
        }
        if (t == 0) attn[j] = red[0] * 0.03125f;
        __syncthreads();
    }
    if (t == 0) {
        float m = -1e30f;
        for (int j = 0; j < Bn; j++) m = fmaxf(m, attn[j]);
        float s = 0.f;
        for (int j = 0; j < Bn; j++) { attn[j] = __expf(attn[j] - m); s += attn[j]; }
        float inv = 1.f / s;
        for (int j = 0; j < Bn; j++) attn[j] *= inv;
    }
    __syncthreads();
    for (int d = t; d < 1024; d += 256) {
        float v = 0.f;
#pragma unroll
        for (int j = 0; j < Bn; j++) v += attn[j] * M1[j * 1024 + d];
        P1[b * 1024 + d] = v;
    }
}

// ---------------------------------------------------------------------------
extern "C" void kernel_launch(void* const* d_in, const int* in_sizes, int n_in,
                              void* d_out, int out_size)
{
    const float* seg0   = (const float*)d_in[0];
    const float* seg1   = (const float*)d_in[1];
    const float* pe     = (const float*)d_in[2];
    const float* Wq_mem = (const float*)d_in[3];
    const float* bq_mem = (const float*)d_in[4];
    const float* Wk_mem = (const float*)d_in[5];
    const float* bk_mem = (const float*)d_in[6];
    const float* Wq     = (const float*)d_in[7];
    const float* bq     = (const float*)d_in[8];
    const float* Wk     = (const float*)d_in[9];
    const float* bk     = (const float*)d_in[10];
    const float* Wv     = (const float*)d_in[11];
    const float* bv     = (const float*)d_in[12];
    const float* Wo     = (const float*)d_in[13];
    const float* bo     = (const float*)d_in[14];
    float* out = (float*)d_out;

    static cudaStream_t s2 = nullptr;
    static cudaEvent_t evFork = nullptr, evWmain = nullptr, evW2 = nullptr,
                       evXD = nullptr, evA = nullptr, evC = nullptr;
    if (s2 == nullptr) {
        cudaStreamCreateWithFlags(&s2, cudaStreamNonBlocking);
        cudaEventCreateWithFlags(&evFork, cudaEventDisableTiming);
        cudaEventCreateWithFlags(&evWmain, cudaEventDisableTiming);
        cudaEventCreateWithFlags(&evW2, cudaEventDisableTiming);
        cudaEventCreateWithFlags(&evXD, cudaEventDisableTiming);
        cudaEventCreateWithFlags(&evA, cudaEventDisableTiming);
        cudaEventCreateWithFlags(&evC, cudaEventDisableTiming);
        cudaFuncSetAttribute(tgemm<0, false>, cudaFuncAttributeMaxDynamicSharedMemorySize, TG_SMEM);
        cudaFuncSetAttribute(tgemm<1, false>, cudaFuncAttributeMaxDynamicSharedMemorySize, TG_SMEM);
        cudaFuncSetAttribute(tgemm<1, true>,  cudaFuncAttributeMaxDynamicSharedMemorySize, TG_SMEM);
        cudaFuncSetAttribute(tgemm<3, true>,  cudaFuncAttributeMaxDynamicSharedMemorySize, TG_SMEM);
        cudaFuncSetAttribute(tgemm<5, true>,  cudaFuncAttributeMaxDynamicSharedMemorySize, TG_SMEM);
    }

    __half *pX, *pXD, *pQ, *pK, *pVt, *pO, *pP;
    __half *pXB, *pQB, *pKB, *pVtB, *pOB, *pPB;
    __half *pWqT, *pWoT, *pWkvT;
    float *pS, *pSB, *pM1, *pS1, *pQn, *pKp, *pP1;
    cudaGetSymbolAddress((void**)&pX, g_X);
    cudaGetSymbolAddress((void**)&pXD, g_XD);
    cudaGetSymbolAddress((void**)&pQ, g_Q);
    cudaGetSymbolAddress((void**)&pK, g_K);
    cudaGetSymbolAddress((void**)&pVt, g_Vt);
    cudaGetSymbolAddress((void**)&pO, g_O);
    cudaGetSymbolAddress((void**)&pP, g_P);
    cudaGetSymbolAddress((void**)&pXB, g_XB);
    cudaGetSymbolAddress((void**)&pQB, g_QB);
    cudaGetSymbolAddress((void**)&pKB, g_KB);
    cudaGetSymbolAddress((void**)&pVtB, g_VtB);
    cudaGetSymbolAddress((void**)&pOB, g_OB);
    cudaGetSymbolAddress((void**)&pPB, g_PB);
    cudaGetSymbolAddress((void**)&pWqT, g_WqT);
    cudaGetSymbolAddress((void**)&pWoT, g_WoT);
    cudaGetSymbolAddress((void**)&pWkvT, g_WkvT);
    cudaGetSymbolAddress((void**)&pS, g_S);
    cudaGetSymbolAddress((void**)&pSB, g_SB);
    cudaGetSymbolAddress((void**)&pM1, g_M1);
    cudaGetSymbolAddress((void**)&pS1, g_S1);
    cudaGetSymbolAddress((void**)&pQn, g_Qn);
    cudaGetSymbolAddress((void**)&pKp, g_Kp);
    cudaGetSymbolAddress((void**)&pP1, g_P1);

    const long long sXD = (long long)NP * Dn;
    const long long sS  = (long long)MQ * NP;
    const long long sXB = (long long)NS * Dn;
    const long long sSB = (long long)NS * NS;

    // ---- FORK at the very start; weight prep split across streams ----
    cudaEventRecord(evFork, 0);
    cudaStreamWaitEvent(s2, evFork, 0);

    dim3 wb(32, 8);
    // main: Wq + Wo in one launch
    wcvt2<<<dim3(32, 32, 2), wb>>>(Wq, pWqT, Wo, pWoT);
    cudaEventRecord(evWmain, 0);
    // s2: Wk + Wv in one launch (into the concatenated KV weight buffer)
    wcvt2<<<dim3(32, 32, 2), wb, 0, s2>>>(Wk, pWkvT, Wv, pWkvT + (size_t)Dn * Dn);
    cudaEventRecord(evW2, s2);

    // === s2: XD build, stage B, Qn ===
    build_x1main<<<dim3(NP * Dn / 512, Bn), 256, 0, s2>>>(seg0, seg1, pXD);
    cudaEventRecord(evXD, s2);
    build_xsh<<<dim3(NS * Dn / 512, Bn), 256, 0, s2>>>(seg1, pe, pXB);
    tgemm<5, true><<<dim3(16, 5, Bn), 256, TG_SMEM, s2>>>(pXB, pWkvT,
        nullptr, pKB, pVtB, bk, bv, nullptr, 0, -1, 8, 1,
        Dn, Dn, Dn, Dn, NS, 1.f, sXB, 0, sXB);
    cudaStreamWaitEvent(s2, evWmain, 0);   // WqT/WoT ready for B's Q/O proj
    tgemm<1, true><<<dim3(8, 1, Bn), 256, TG_SMEM, s2>>>(pXB + 512 * Dn, pWqT,
        nullptr, pQB + 512 * Dn, nullptr, bq, nullptr, nullptr, 0, -1, 0, 1,
        Dn, Dn, Dn, Dn, 0, 1.f, sXB, 0, sXB);
    tgemm<0, false><<<dim3(5, 1, Bn), 256, TG_SMEM, s2>>>(pQB + 512 * Dn, pKB,
        pSB + 512 * NS, nullptr, nullptr, nullptr, nullptr, nullptr, 0, -1, 0, 1,
        Dn, Dn, Dn, NS, 0, 0.03125f, sXB, sXB, sSB);
    softmax_reg<<<dim3(128, Bn), 256, 0, s2>>>(pSB, pPB, 514, NS, NS, 512);
    tgemm<1, false><<<dim3(8, 1, Bn), 256, TG_SMEM, s2>>>(pPB + 512 * NS, pVtB,
        nullptr, pOB + 512 * Dn, nullptr, nullptr, nullptr, nullptr, 0, -1, 0, 1,
        576, NS, NS, Dn, 0, 1.f, sSB, sXB, sXB);
    tgemm<3, true><<<dim3(8, 1, Bn), 256, TG_SMEM, s2>>>(pOB + 512 * Dn, pWoT,
        out, nullptr, nullptr, bo, nullptr, pS1, 0, 0, 0, 1,
        Dn, Dn, Dn, Dn, 0, 1.f, sXB, 0, 0);
    sgemm<false, true><<<dim3(Dn / 128, 1), 256, 0, s2>>>(pS1, Wq_mem, pQn,
                                                          bq_mem, Dn, Dn, 1.f);

    // === main: stage A ===
    build_x0h<<<dim3(NP * Dn / 512, Bn), 256>>>(seg0, pX);
    {
        const int n = 2050, KT = 2112;
        tgemm<1, true><<<dim3(8, 16, Bn), 256, TG_SMEM>>>(pX + 33 * Dn, pWqT,
            nullptr, pQ, nullptr, bq, nullptr, nullptr, 0, -1, 0, 1,
            Dn, Dn, Dn, Dn, 0, 1.f, sXD, 0, sXD);
        cudaStreamWaitEvent(0, evW2, 0);   // WkvT ready
        tgemm<5, true><<<dim3(16, 17, Bn), 256, TG_SMEM>>>(pX, pWkvT,
            nullptr, pK, pVt, bk, bv, nullptr, 0, -1, 8, 1,
            Dn, Dn, Dn, Dn, NP, 1.f, sXD, 0, sXD);
        tgemm<0, false><<<dim3(17, 16, Bn), 256, TG_SMEM>>>(pQ, pK, pS,
            nullptr, nullptr, nullptr, nullptr, nullptr, 0, -1, 0, 1,
            Dn, Dn, Dn, NP, 0, 0.03125f, sXD, sXD, sS);
        softmax_reg<<<dim3(MQ, Bn), 256>>>(pS, pP, n, NP, MQ, 0);
        tgemm<1, false><<<dim3(8, 16, Bn), 256, TG_SMEM>>>(pP, pVt,
            nullptr, pO, nullptr, nullptr, nullptr, nullptr, 0, -1, 0, 1,
            KT, NP, NP, Dn, 0, 1.f, sS, sXD, sXD);
        tgemm<3, true><<<dim3(8, 16, Bn), 256, TG_SMEM>>>(pO, pWoT,
            out, nullptr, nullptr, bo, nullptr, pM1, 2016, 2016, 0, 1,
            Dn, Dn, Dn, Dn, 0, 1.f, sXD, 0, (long long)2016 * Dn);
    }
    cudaEventRecord(evA, 0);

    // === s2: stage C (needs M1 from A) + P1 patch into XD ===
    cudaStreamWaitEvent(s2, evA, 0);
    sgemm<false, true><<<dim3(Dn / 128, 1), 256, 0, s2>>>(pM1, Wk_mem, pKp,
                                                          bk_mem, Dn, Dn, 1.f);
    mem_attn<<<Bn, 256, 0, s2>>>(pQn, pKp, pM1, pP1);
    build_x1_p1<<<32, 256, 0, s2>>>(pP1, pXD);
    cudaEventRecord(evC, s2);

    // === main: stage D (P1-independent GEMMs overlap stage C) ===
    cudaStreamWaitEvent(0, evXD, 0);
    {
        const int n = 2082, KT = 2112;
        // Q projection: rows 33..2080, never touches P1 rows
        tgemm<1, true><<<dim3(8, 16, Bn), 256, TG_SMEM>>>(pXD + 33 * Dn, pWqT,
            nullptr, pQ, nullptr, bq, nullptr, nullptr, 0, -1, 0, 1,
            Dn, Dn, Dn, Dn, 0, 1.f, sXD, 0, sXD);
        // merged KV, row-tiles 1..15 (no P1 rows)
        tgemm<5, true><<<dim3(16, 15, Bn), 256, TG_SMEM>>>(pXD + 128 * Dn,
            pWkvT, nullptr, pK + 128 * Dn, pVt + 128, bk, bv, nullptr,
            0, -1, 8, 1, Dn, Dn, Dn, Dn, NP, 1.f, sXD, 0, sXD);
        // P1-dependent row-tiles 0 and 16 in ONE launch (ytstep=16)
        cudaStreamWaitEvent(0, evC, 0);
        tgemm<5, true><<<dim3(16, 2, Bn), 256, TG_SMEM>>>(pXD, pWkvT,
            nullptr, pK, pVt, bk, bv, nullptr, 0, -1, 8, 16,
            Dn, Dn, Dn, Dn, NP, 1.f, sXD, 0, sXD);
        tgemm<0, false><<<dim3(17, 16, Bn), 256, TG_SMEM>>>(pQ, pK, pS,
            nullptr, nullptr, nullptr, nullptr, nullptr, 0, -1, 0, 1,
            Dn, Dn, Dn, NP, 0, 0.03125f, sXD, sXD, sS);
        softmax_reg<<<dim3(MQ, Bn), 256>>>(pS, pP, n, NP, MQ, 0);
        tgemm<1, false><<<dim3(8, 16, Bn), 256, TG_SMEM>>>(pP, pVt,
            nullptr, pO, nullptr, nullptr, nullptr, nullptr, 0, -1, 0, 1,
            KT, NP, NP, Dn, 0, 1.f, sS, sXD, sXD);
        tgemm<3, true><<<dim3(8, 16, Bn), 256, TG_SMEM>>>(pO, pWoT,
            out + (long long)Bn * 2016 * Dn, nullptr, nullptr, bo, nullptr,
            pM1, 2048, -1, 0, 1, Dn, Dn, Dn, Dn, 0, 1.f, sXD, 0,
            (long long)2048 * Dn);
    }
}